// round 1
// baseline (speedup 1.0000x reference)
#include <cuda_runtime.h>

#define NB 8
#define NP 4096
#define NG 96
#define NT 1024
#define CPT (NP / NT)          // 4 columns per thread
#define BIGF 1e9f

// 12.6 MB scratch: transposed cost matrix, L2-resident.
__device__ float g_costT[NB][NG][NP];

// ---------------------------------------------------------------------------
// Build costT[b][g][p] = center_dist[b][p][g] - 2 * gious[b][p][g]
// Tiled transpose: coalesced reads and writes.
// ---------------------------------------------------------------------------
__global__ void build_cost_kernel(const float* __restrict__ cd,
                                  const float* __restrict__ gi) {
    __shared__ float tile[32][33];
    int b  = blockIdx.z;
    int p0 = blockIdx.x * 32;
    int g0 = blockIdx.y * 32;
    int tx = threadIdx.x, ty = threadIdx.y;

    #pragma unroll
    for (int r = ty; r < 32; r += 8) {
        int p = p0 + r;
        int g = g0 + tx;
        size_t idx = ((size_t)b * NP + p) * NG + g;
        tile[r][tx] = cd[idx] - 2.0f * gi[idx];
    }
    __syncthreads();
    #pragma unroll
    for (int r = ty; r < 32; r += 8) {
        int g = g0 + r;
        int p = p0 + tx;
        g_costT[b][g][p] = tile[tx][r];
    }
}

// ---------------------------------------------------------------------------
// One CTA per batch: exact JV shortest-augmenting-path LSA on costT[b]
// (rows = GT 0..nactual-1, cols = 4096 proposals), then scatter epilogue.
// ---------------------------------------------------------------------------

// shared layout sizes (bytes)
#define SMEM_BYTES (4*NP*4 /*v,shortest,path,row4col*/ \
                    + NG*4*2 /*u,col4row*/            \
                    + 32*4*2 /*redv,redi*/            \
                    + NP /*SC*/ + NG /*SR*/ + 16 /*scalars*/)

__global__ void __launch_bounds__(NT, 1)
lsa_kernel(const int* __restrict__ nactual, float* __restrict__ out) {
    extern __shared__ unsigned char smem[];
    float* v         = (float*)smem;                   // NP
    float* shortest  = v + NP;                         // NP
    int*   path      = (int*)(shortest + NP);          // NP
    int*   row4col   = path + NP;                      // NP
    float* u         = (float*)(row4col + NP);         // NG
    int*   col4row   = (int*)(u + NG);                 // NG
    float* redv      = (float*)(col4row + NG);         // 32
    int*   redi      = (int*)(redv + 32);              // 32
    unsigned char* SC = (unsigned char*)(redi + 32);   // NP
    unsigned char* SR = SC + NP;                       // NG
    int*   s_int     = (int*)(SR + NG);                // scalars (4-byte aligned)
    int*   s_cur     = &s_int[0];
    int*   s_sink    = &s_int[1];
    float* s_minval  = (float*)&s_int[2];

    const int b   = blockIdx.x;
    const int tid = threadIdx.x;
    const int nact = nactual[b];

    // per-batch init
    #pragma unroll
    for (int k = 0; k < CPT; ++k) {
        int j = tid + k * NT;
        v[j] = 0.0f;
        row4col[j] = -1;
    }
    if (tid < NG) { u[tid] = 0.0f; col4row[tid] = -1; }
    __syncthreads();

    for (int i = 0; i < nact; ++i) {
        // per-augmentation init
        #pragma unroll
        for (int k = 0; k < CPT; ++k) {
            int j = tid + k * NT;
            shortest[j] = BIGF;
            path[j] = -1;
            SC[j] = 0;
        }
        if (tid < NG) SR[tid] = 0;
        if (tid == 0) { *s_cur = i; *s_minval = 0.0f; *s_sink = -1; }
        __syncthreads();

        // ---- Dijkstra-style shortest augmenting path ----
        while (true) {
            const int   cur    = *s_cur;
            const float minval = *s_minval;
            if (tid == 0) SR[cur] = 1;
            const float ucur = u[cur];
            const float* __restrict__ crow = &g_costT[b][cur][0];

            float lv = 3.0e38f;
            int   li = NP;
            #pragma unroll
            for (int k = 0; k < CPT; ++k) {
                int j = tid + k * NT;
                float cand;
                if (!SC[j]) {
                    float sh  = shortest[j];
                    float red = ((minval + crow[j]) - ucur) - v[j];
                    if (red < sh) { sh = red; shortest[j] = red; path[j] = cur; }
                    cand = sh;
                } else {
                    cand = BIGF;
                }
                // strict < keeps lowest index within this thread (j ascending)
                if (cand < lv) { lv = cand; li = j; }
            }

            // warp argmin (value, then lowest index)
            #pragma unroll
            for (int off = 16; off > 0; off >>= 1) {
                float ov = __shfl_down_sync(0xffffffffu, lv, off);
                int   oi = __shfl_down_sync(0xffffffffu, li, off);
                if (ov < lv || (ov == lv && oi < li)) { lv = ov; li = oi; }
            }
            const int lane = tid & 31, wid = tid >> 5;
            if (lane == 0) { redv[wid] = lv; redi[wid] = li; }
            __syncthreads();
            if (wid == 0) {
                lv = redv[lane]; li = redi[lane];
                #pragma unroll
                for (int off = 16; off > 0; off >>= 1) {
                    float ov = __shfl_down_sync(0xffffffffu, lv, off);
                    int   oi = __shfl_down_sync(0xffffffffu, li, off);
                    if (ov < lv || (ov == lv && oi < li)) { lv = ov; li = oi; }
                }
                if (lane == 0) {
                    int j = li;
                    *s_minval = lv;
                    SC[j] = 1;
                    int r = row4col[j];
                    if (r < 0) *s_sink = j;   // free column: sink found
                    else       *s_cur  = r;   // continue from assigned row
                }
            }
            __syncthreads();
            if (*s_sink >= 0) break;
        }

        // ---- dual (potential) updates, exactly as scipy rectangular_lsap ----
        const float minval = *s_minval;
        const int   sinkj  = *s_sink;
        if (tid < NG) {
            if (tid == i)      u[tid] = u[tid] + minval;
            else if (SR[tid])  u[tid] = (u[tid] + minval) - shortest[col4row[tid]];
        }
        #pragma unroll
        for (int k = 0; k < CPT; ++k) {
            int j = tid + k * NT;
            if (SC[j]) v[j] = v[j] - (minval - shortest[j]);
        }
        __syncthreads();

        // ---- augment: flip alternating path from sink back to row i ----
        if (tid == 0) {
            int j = sinkj;
            while (true) {
                int r = path[j];
                row4col[j] = r;
                int jn = col4row[r];
                col4row[r] = j;
                if (r == i) break;
                j = jn;
            }
        }
        __syncthreads();
    }

    // ---- epilogue: scatter outputs ----
    float* out_inds = out;                 // [NB*NP] per_prop_gt_inds (as float)
    float* out_mask = out + NB * NP;       // [NB*NP] proposal_matched_mask
    #pragma unroll
    for (int k = 0; k < CPT; ++k) {
        int j = tid + k * NT;
        out_inds[b * NP + j] = 0.0f;
        out_mask[b * NP + j] = 0.0f;
    }
    __syncthreads();
    if (tid < nact) {
        int j = col4row[tid];              // assigned proposal for GT row `tid`
        out_inds[b * NP + j] = (float)tid;
        out_mask[b * NP + j] = 1.0f;
    }
}

// ---------------------------------------------------------------------------
extern "C" void kernel_launch(void* const* d_in, const int* in_sizes, int n_in,
                              void* d_out, int out_size) {
    const float* cd   = (const float*)d_in[0];   // center_dist [8,4096,96] f32
    const float* gi   = (const float*)d_in[1];   // gious       [8,4096,96] f32
    const int*   nact = (const int*)d_in[2];     // nactual_gt  [8] i32

    dim3 tgrid(NP / 32, NG / 32, NB);
    build_cost_kernel<<<tgrid, dim3(32, 8)>>>(cd, gi);

    cudaFuncSetAttribute(lsa_kernel,
                         cudaFuncAttributeMaxDynamicSharedMemorySize,
                         SMEM_BYTES);
    lsa_kernel<<<NB, NT, SMEM_BYTES>>>(nact, (float*)d_out);
}

// round 3
// speedup vs baseline: 9.4009x; 9.4009x over previous
#include <cuda_runtime.h>

#define NB 8
#define NP 4096
#define NG 96
#define NT 1024
#define CPT (NP / NT)          // 4 columns per thread
#define BIGF 1e9f

// 12.6 MB scratch: transposed cost matrix, L2-resident.
__device__ float g_costT[NB][NG][NP];
__device__ float g_u0[NB][NG];   // row minima (initial duals)
__device__ int   g_j0[NB][NG];   // row argmin columns

// ---------------------------------------------------------------------------
// Build costT[b][g][p] = center_dist[b][p][g] - 2 * gious[b][p][g]
// Tiled transpose: coalesced reads and writes.
// ---------------------------------------------------------------------------
__global__ void build_cost_kernel(const float* __restrict__ cd,
                                  const float* __restrict__ gi) {
    __shared__ float tile[32][33];
    int b  = blockIdx.z;
    int p0 = blockIdx.x * 32;
    int g0 = blockIdx.y * 32;
    int tx = threadIdx.x, ty = threadIdx.y;

    #pragma unroll
    for (int r = ty; r < 32; r += 8) {
        int p = p0 + r;
        int g = g0 + tx;
        size_t idx = ((size_t)b * NP + p) * NG + g;
        tile[r][tx] = cd[idx] - 2.0f * gi[idx];
    }
    __syncthreads();
    #pragma unroll
    for (int r = ty; r < 32; r += 8) {
        int g = g0 + r;
        int p = p0 + tx;
        g_costT[b][g][p] = tile[tx][r];
    }
}

// ---------------------------------------------------------------------------
// Row minima + argmin (lowest index on ties): one block per (row, batch).
// ---------------------------------------------------------------------------
__global__ void rowmin_kernel() {
    const int b = blockIdx.y;
    const int g = blockIdx.x;
    const int tid = threadIdx.x;
    const float* __restrict__ row = &g_costT[b][g][0];

    float lv = 3.0e38f;
    int   li = NP;
    #pragma unroll
    for (int k = 0; k < NP / 256; ++k) {
        int j = tid + k * 256;           // ascending per thread -> strict <
        float val = row[j];
        if (val < lv) { lv = val; li = j; }
    }
    #pragma unroll
    for (int off = 16; off > 0; off >>= 1) {
        float ov = __shfl_down_sync(0xffffffffu, lv, off);
        int   oi = __shfl_down_sync(0xffffffffu, li, off);
        if (ov < lv || (ov == lv && oi < li)) { lv = ov; li = oi; }
    }
    __shared__ float sv[8];
    __shared__ int   si[8];
    const int lane = tid & 31, wid = tid >> 5;
    if (lane == 0) { sv[wid] = lv; si[wid] = li; }
    __syncthreads();
    if (tid == 0) {
        lv = sv[0]; li = si[0];
        #pragma unroll
        for (int w = 1; w < 8; ++w) {
            if (sv[w] < lv || (sv[w] == lv && si[w] < li)) { lv = sv[w]; li = si[w]; }
        }
        g_u0[b][g] = lv;
        g_j0[b][g] = li;
    }
}

// ---------------------------------------------------------------------------
// One CTA per batch: greedy (JV row-reduction) init, then exact shortest
// augmenting path for the few conflicted rows, then scatter epilogue.
// ---------------------------------------------------------------------------

// shared layout sizes (bytes)
#define SMEM_BYTES (4*NP*4 /*v,shortest,path,row4col*/ \
                    + NG*4*3 /*u,col4row,jmin*/        \
                    + 32*4*2 /*redv,redi*/             \
                    + NP /*SC*/ + NG /*SR*/ + 16 /*scalars*/)

__global__ void __launch_bounds__(NT, 1)
lsa_kernel(const int* __restrict__ nactual, float* __restrict__ out) {
    extern __shared__ unsigned char smem[];
    float* v         = (float*)smem;                   // NP
    float* shortest  = v + NP;                         // NP
    int*   path      = (int*)(shortest + NP);          // NP (reused as colwin)
    int*   row4col   = path + NP;                      // NP
    float* u         = (float*)(row4col + NP);         // NG
    int*   col4row   = (int*)(u + NG);                 // NG
    int*   jmin_s    = col4row + NG;                   // NG
    float* redv      = (float*)(jmin_s + NG);          // 32
    int*   redi      = (int*)(redv + 32);              // 32
    unsigned char* SC = (unsigned char*)(redi + 32);   // NP
    unsigned char* SR = SC + NP;                       // NG
    int*   s_int     = (int*)(SR + NG);                // scalars (4-byte aligned)
    int*   s_cur     = &s_int[0];
    int*   s_sink    = &s_int[1];
    float* s_minval  = (float*)&s_int[2];

    const int b   = blockIdx.x;
    const int tid = threadIdx.x;
    const int nact = nactual[b];

    // ---- per-batch init + greedy (row-reduction) assignment ----
    int* colwin = path;  // alias during greedy phase
    #pragma unroll
    for (int k = 0; k < CPT; ++k) {
        int j = tid + k * NT;
        v[j] = 0.0f;
        row4col[j] = -1;
        colwin[j] = 0x7fffffff;
    }
    if (tid < NG) {
        u[tid]       = g_u0[b][tid];
        jmin_s[tid]  = g_j0[b][tid];
        col4row[tid] = -1;
    }
    __syncthreads();
    if (tid < nact) atomicMin(&colwin[jmin_s[tid]], tid);
    __syncthreads();
    if (tid < nact) {
        int j = jmin_s[tid];
        if (colwin[j] == tid) {           // lowest claimant wins (== sequential greedy)
            col4row[tid] = j;
            row4col[j]   = tid;
        }
    }
    __syncthreads();

    // ---- shortest augmenting path for each unassigned row ----
    for (int i = 0; i < nact; ++i) {
        if (col4row[i] >= 0) continue;    // greedily assigned

        // per-augmentation init
        #pragma unroll
        for (int k = 0; k < CPT; ++k) {
            int j = tid + k * NT;
            shortest[j] = BIGF;
            path[j] = -1;
            SC[j] = 0;
        }
        if (tid < NG) SR[tid] = 0;
        if (tid == 0) { *s_cur = i; *s_minval = 0.0f; *s_sink = -1; }
        __syncthreads();

        // ---- Dijkstra-style shortest augmenting path ----
        while (true) {
            const int   cur    = *s_cur;
            const float minval = *s_minval;
            if (tid == 0) SR[cur] = 1;
            const float ucur = u[cur];
            const float* __restrict__ crow = &g_costT[b][cur][0];

            float lv = 3.0e38f;
            int   li = NP;
            #pragma unroll
            for (int k = 0; k < CPT; ++k) {
                int j = tid + k * NT;
                float cand;
                if (!SC[j]) {
                    float sh  = shortest[j];
                    float red = ((minval + crow[j]) - ucur) - v[j];
                    if (red < sh) { sh = red; shortest[j] = red; path[j] = cur; }
                    cand = sh;
                } else {
                    cand = BIGF;
                }
                if (cand < lv) { lv = cand; li = j; }  // ascending j: keeps lowest
            }

            // warp argmin (value, then lowest index)
            #pragma unroll
            for (int off = 16; off > 0; off >>= 1) {
                float ov = __shfl_down_sync(0xffffffffu, lv, off);
                int   oi = __shfl_down_sync(0xffffffffu, li, off);
                if (ov < lv || (ov == lv && oi < li)) { lv = ov; li = oi; }
            }
            const int lane = tid & 31, wid = tid >> 5;
            if (lane == 0) { redv[wid] = lv; redi[wid] = li; }
            __syncthreads();
            if (wid == 0) {
                lv = redv[lane]; li = redi[lane];
                #pragma unroll
                for (int off = 16; off > 0; off >>= 1) {
                    float ov = __shfl_down_sync(0xffffffffu, lv, off);
                    int   oi = __shfl_down_sync(0xffffffffu, li, off);
                    if (ov < lv || (ov == lv && oi < li)) { lv = ov; li = oi; }
                }
                if (lane == 0) {
                    int j = li;
                    *s_minval = lv;
                    SC[j] = 1;
                    int r = row4col[j];
                    if (r < 0) *s_sink = j;   // free column: sink found
                    else       *s_cur  = r;   // continue from assigned row
                }
            }
            __syncthreads();
            if (*s_sink >= 0) break;
        }

        // ---- dual (potential) updates, exactly as scipy rectangular_lsap ----
        const float minval = *s_minval;
        const int   sinkj  = *s_sink;
        if (tid < NG) {
            if (tid == i)      u[tid] = u[tid] + minval;
            else if (SR[tid])  u[tid] = (u[tid] + minval) - shortest[col4row[tid]];
        }
        #pragma unroll
        for (int k = 0; k < CPT; ++k) {
            int j = tid + k * NT;
            if (SC[j]) v[j] = v[j] - (minval - shortest[j]);
        }
        __syncthreads();

        // ---- augment: flip alternating path from sink back to row i ----
        if (tid == 0) {
            int j = sinkj;
            while (true) {
                int r = path[j];
                row4col[j] = r;
                int jn = col4row[r];
                col4row[r] = j;
                if (r == i) break;
                j = jn;
            }
        }
        __syncthreads();
    }

    // ---- epilogue: scatter outputs ----
    float* out_inds = out;                 // [NB*NP] per_prop_gt_inds (as float)
    float* out_mask = out + NB * NP;       // [NB*NP] proposal_matched_mask
    #pragma unroll
    for (int k = 0; k < CPT; ++k) {
        int j = tid + k * NT;
        out_inds[b * NP + j] = 0.0f;
        out_mask[b * NP + j] = 0.0f;
    }
    __syncthreads();
    if (tid < nact) {
        int j = col4row[tid];              // assigned proposal for GT row `tid`
        out_inds[b * NP + j] = (float)tid;
        out_mask[b * NP + j] = 1.0f;
    }
}

// ---------------------------------------------------------------------------
extern "C" void kernel_launch(void* const* d_in, const int* in_sizes, int n_in,
                              void* d_out, int out_size) {
    const float* cd   = (const float*)d_in[0];   // center_dist [8,4096,96] f32
    const float* gi   = (const float*)d_in[1];   // gious       [8,4096,96] f32
    const int*   nact = (const int*)d_in[2];     // nactual_gt  [8] i32

    dim3 tgrid(NP / 32, NG / 32, NB);
    build_cost_kernel<<<tgrid, dim3(32, 8)>>>(cd, gi);

    rowmin_kernel<<<dim3(NG, NB), 256>>>();

    cudaFuncSetAttribute(lsa_kernel,
                         cudaFuncAttributeMaxDynamicSharedMemorySize,
                         SMEM_BYTES);
    lsa_kernel<<<NB, NT, SMEM_BYTES>>>(nact, (float*)d_out);
}